// round 10
// baseline (speedup 1.0000x reference)
#include <cuda_runtime.h>
#include <cstdint>

// Problem constants (fixed by the reference)
#define B_ 32
#define D_ 64
#define T_ 4096
#define K_ 512
#define N_ (B_ * T_)        // 131072 tokens
#define NQ_ (B_ * D_ * T_)  // 8388608 quantized elements
#define CAP_ 20

// Scratch (device globals: no allocation allowed)
__device__ unsigned int g_maxz_bits;
__device__ unsigned int g_maxc_bits;
__device__ float        g_cbnorm[K_];
__device__ int2         g_cnsc[K_];            // (cn_int - ch, 2*ch), ch = ceil(sc/2)
__device__ __align__(16) int g_cbimg[K_ * 16];
__device__ float        g_partial[128];
__device__ unsigned int g_count;

// ---------------------------------------------------------------------------
// prep 0: global max |z|
// ---------------------------------------------------------------------------
__global__ void prep_z_kernel(const float* __restrict__ z) {
    const float4* z4 = reinterpret_cast<const float4*>(z);
    float m = 0.0f;
    for (int j = blockIdx.x * blockDim.x + threadIdx.x; j < NQ_ / 4;
         j += gridDim.x * blockDim.x) {
        float4 v = z4[j];
        m = fmaxf(m, fmaxf(fmaxf(fabsf(v.x), fabsf(v.y)),
                           fmaxf(fabsf(v.z), fabsf(v.w))));
    }
#pragma unroll
    for (int o = 16; o > 0; o >>= 1) m = fmaxf(m, __shfl_xor_sync(0xffffffffu, m, o));
    if ((threadIdx.x & 31) == 0) atomicMax(&g_maxz_bits, __float_as_uint(m));
}

// prep 1: exact norms (canonical fmaf order, proven rel_err = 0.0) + max |c|
__global__ void prep_cb1_kernel(const float* __restrict__ cb) {
    int k = blockIdx.x * blockDim.x + threadIdx.x;
    if (k < K_) {
        const float* r = cb + k * D_;
        float a = 0.0f, mx = 0.0f;
#pragma unroll
        for (int i = 0; i < D_; ++i) {
            a = fmaf(r[i], r[i], a);
            mx = fmaxf(mx, fabsf(r[i]));
        }
        g_cbnorm[k] = a;
        atomicMax(&g_maxc_bits, __float_as_uint(mx));
    }
}

// prep 2: int8 image, (cn_int - ch, 2*ch)
__global__ void prep_cb2_kernel(const float* __restrict__ cb) {
    int k = blockIdx.x * blockDim.x + threadIdx.x;
    if (k >= K_) return;
    const float maxz = __uint_as_float(g_maxz_bits);
    const float maxc = __uint_as_float(g_maxc_bits);
    const float inv_sc = (maxc > 0.0f) ? 127.0f / maxc : 0.0f;
    const float* r = cb + k * D_;
    int sa = 0;
#pragma unroll
    for (int j = 0; j < 16; ++j) {
        int b0 = min(127, max(-127, __float2int_rn(r[4 * j + 0] * inv_sc)));
        int b1 = min(127, max(-127, __float2int_rn(r[4 * j + 1] * inv_sc)));
        int b2 = min(127, max(-127, __float2int_rn(r[4 * j + 2] * inv_sc)));
        int b3 = min(127, max(-127, __float2int_rn(r[4 * j + 3] * inv_sc)));
        sa += abs(b0) + abs(b1) + abs(b2) + abs(b3);
        g_cbimg[k * 16 + j] = (b0 & 0xFF) | ((b1 & 0xFF) << 8) |
                              ((b2 & 0xFF) << 16) | ((b3 & 0xFF) << 24);
    }
    const float denom = 2.0f * (maxz * (1.0f / 127.0f)) * (maxc * (1.0f / 127.0f));
    float v = (denom > 0.0f) ? g_cbnorm[k] / denom : 0.0f;
    int cni = __float2int_rn(fminf(fmaxf(v, -2.0e9f), 2.0e9f));
    int ch  = (sa + 1) >> 1;                    // ceil(sc/2): conservative
    g_cnsc[k] = make_int2(cni - ch, 2 * ch);
}

// ---------------------------------------------------------------------------
// smem layout. CBF rows are 272B: 64 fp32 codebook + int2(cnlo,two_ch) + cn_fp.
// ---------------------------------------------------------------------------
#define SM_IMG   0                            // 2048 int4         =  32768
#define SM_CBF   32768                        // 512 * 272         = 139264
#define SM_CAND  172032                       // 1024 * 20 * 2B    =  40960
#define SM_WSUM  212992                       // 16 float          =     64
#define SM_RD    213056                       // 128 double        =   1024
#define SM_LAST  214080                       // int (+pad)        =     16
#define SM_TOT   214096

// Exact fp32 distance from padded smem codebook (row = 272B = 17 float4).
// Bit-identical to the proven round-0 formula.
__device__ __forceinline__ float exact_dist_sm(const float* zr, float A,
                                               const char* __restrict__ smbase,
                                               int k) {
    const float4* cp = reinterpret_cast<const float4*>(smbase + SM_CBF + k * 272);
    float s0 = 0.f, s1 = 0.f, s2 = 0.f, s3 = 0.f;
#pragma unroll
    for (int i = 0; i < 16; ++i) {
        float4 c = cp[i];
        s0 = fmaf(zr[4 * i + 0], c.x, s0);
        s1 = fmaf(zr[4 * i + 1], c.y, s1);
        s2 = fmaf(zr[4 * i + 2], c.z, s2);
        s3 = fmaf(zr[4 * i + 3], c.w, s3);
    }
    float dot = __fadd_rn(__fadd_rn(s0, s1), __fadd_rn(s2, s3));
    float cn  = *reinterpret_cast<const float*>(smbase + SM_CBF + k * 272 + 264);
    return __fadd_rn(__fadd_rn(A, cn), -__fmul_rn(2.0f, dot));
}

// ---------------------------------------------------------------------------
// fused VQ kernel: 512 thd, 2 tokens/thread, grid 128 (single wave).
// ---------------------------------------------------------------------------
__global__ __launch_bounds__(512, 1)
void vq_kernel(const float* __restrict__ z,
               const float* __restrict__ cb,
               float* __restrict__ out_q,
               float* __restrict__ out_i,
               float* __restrict__ loss_ptr) {
    extern __shared__ char sm[];
    int4*           s_img  = reinterpret_cast<int4*>(sm + SM_IMG);
    unsigned short* s_cand = reinterpret_cast<unsigned short*>(sm + SM_CAND);
    float*          s_wsum = reinterpret_cast<float*>(sm + SM_WSUM);
    double*         s_rd   = reinterpret_cast<double*>(sm + SM_RD);
    int*            s_last = reinterpret_cast<int*>(sm + SM_LAST);

    const int tid  = threadIdx.x;
    const int wid  = tid >> 5;
    const int lane = tid & 31;

    // ---- stage: int8 image; CBF rows (codebook + embedded metadata) ----
    {
        const int4* src = reinterpret_cast<const int4*>(g_cbimg);
#pragma unroll
        for (int i = tid; i < K_ * 4; i += 512) s_img[i] = src[i];
        const float4* cb4 = reinterpret_cast<const float4*>(cb);
        float4* dst = reinterpret_cast<float4*>(sm + SM_CBF);
#pragma unroll
        for (int i = tid; i < K_ * 16; i += 512)
            dst[(i >> 4) * 17 + (i & 15)] = cb4[i];
        // metadata slot: int2 at +256, cn fp32 at +264
        *reinterpret_cast<int2*>(sm + SM_CBF + tid * 272 + 256) = g_cnsc[tid];
        *reinterpret_cast<float*>(sm + SM_CBF + tid * 272 + 264) = g_cbnorm[tid];
    }

    // ---- phase 1: quantize both tokens (low reg footprint) ----
    const int nbase = blockIdx.x * 1024;
    const int bidx  = nbase >> 12;                 // batch (same for all 1024)
    const float* zb = z + ((size_t)bidx << 18);
    const int t0 = (nbase & 4095) + tid;           // token0 col
    const int t1 = t0 + 512;                       // token1 col

    const float maxz = __uint_as_float(g_maxz_bits);
    const float inv_sz = (maxz > 0.0f) ? 127.0f / maxz : 0.0f;

    int zp0[16], zp1[16];
    int sabs0 = 0, sabs1 = 0;
#pragma unroll
    for (int j = 0; j < 16; ++j) {
        int p0 = 0, p1 = 0;
#pragma unroll
        for (int q = 0; q < 4; ++q) {
            float x0 = zb[((size_t)(4 * j + q) << 12) + t0];
            float x1 = zb[((size_t)(4 * j + q) << 12) + t1];
            int b0 = min(127, max(-127, __float2int_rn(x0 * inv_sz)));
            int b1 = min(127, max(-127, __float2int_rn(x1 * inv_sz)));
            sabs0 += abs(b0);
            sabs1 += abs(b1);
            p0 |= ((-b0) & 0xFF) << (q * 8);
            p1 |= ((-b1) & 0xFF) << (q * 8);
        }
        zp0[j] = p0;
        zp1[j] = p1;
    }

    // sound margins (undoubled units; see derivation in commit msg)
    const float maxc  = __uint_as_float(g_maxc_bits);
    const float denom = 2.0f * (maxz * (1.0f / 127.0f)) * (maxc * (1.0f / 127.0f));
    const float slack_f = (denom > 0.0f) ? 2.0e-4f / denom : 4.0e9f;
    const int   slack   = (slack_f < 1.0e9f) ? ((int)slack_f + 2) : (1 << 27);
    long long ml0 = (long long)sabs0 + 2LL * slack + 128;
    long long ml1 = (long long)sabs1 + 2LL * slack + 128;
    const int M0 = (int)((ml0 < (1LL << 29)) ? ml0 : (1LL << 29));
    const int M1 = (int)((ml1 < (1LL << 29)) ? ml1 : (1LL << 29));

    __syncthreads();

    // ---- phase 2: dual-token dp4a screen -> candidate lists ----
    int thr0 = 0x7FFFFFFF, thr1 = 0x7FFFFFFF;
    int cnt0 = 0, cnt1 = 0;
    unsigned short* cl0 = s_cand + tid * CAP_;
    unsigned short* cl1 = s_cand + (512 + tid) * CAP_;

#pragma unroll 4
    for (int k = 0; k < K_; ++k) {
        int4 c0 = s_img[4 * k + 0], c1 = s_img[4 * k + 1];
        int4 c2 = s_img[4 * k + 2], c3 = s_img[4 * k + 3];
        int2 cs = *reinterpret_cast<const int2*>(sm + SM_CBF + k * 272 + 256);

        int a0 = cs.x, a1 = 0, a2 = 0, a3 = 0;
        a0 = __dp4a(zp0[0],  c0.x, a0);  a1 = __dp4a(zp0[1],  c0.y, a1);
        a2 = __dp4a(zp0[2],  c0.z, a2);  a3 = __dp4a(zp0[3],  c0.w, a3);
        a0 = __dp4a(zp0[4],  c1.x, a0);  a1 = __dp4a(zp0[5],  c1.y, a1);
        a2 = __dp4a(zp0[6],  c1.z, a2);  a3 = __dp4a(zp0[7],  c1.w, a3);
        a0 = __dp4a(zp0[8],  c2.x, a0);  a1 = __dp4a(zp0[9],  c2.y, a1);
        a2 = __dp4a(zp0[10], c2.z, a2);  a3 = __dp4a(zp0[11], c2.w, a3);
        a0 = __dp4a(zp0[12], c3.x, a0);  a1 = __dp4a(zp0[13], c3.y, a1);
        a2 = __dp4a(zp0[14], c3.z, a2);  a3 = __dp4a(zp0[15], c3.w, a3);
        int s0 = (a0 + a1) + (a2 + a3);          // = sigma - ch (seeded)

        int b0 = cs.x, b1 = 0, b2 = 0, b3 = 0;
        b0 = __dp4a(zp1[0],  c0.x, b0);  b1 = __dp4a(zp1[1],  c0.y, b1);
        b2 = __dp4a(zp1[2],  c0.z, b2);  b3 = __dp4a(zp1[3],  c0.w, b3);
        b0 = __dp4a(zp1[4],  c1.x, b0);  b1 = __dp4a(zp1[5],  c1.y, b1);
        b2 = __dp4a(zp1[6],  c1.z, b2);  b3 = __dp4a(zp1[7],  c1.w, b3);
        b0 = __dp4a(zp1[8],  c2.x, b0);  b1 = __dp4a(zp1[9],  c2.y, b1);
        b2 = __dp4a(zp1[10], c2.z, b2);  b3 = __dp4a(zp1[11], c2.w, b3);
        b0 = __dp4a(zp1[12], c3.x, b0);  b1 = __dp4a(zp1[13], c3.y, b1);
        b2 = __dp4a(zp1[14], c3.z, b2);  b3 = __dp4a(zp1[15], c3.w, b3);
        int s1 = (b0 + b1) + (b2 + b3);

        if (s0 <= thr0) {
            if (cnt0 < CAP_) cl0[cnt0] = (unsigned short)k;
            ++cnt0;
        }
        thr0 = min(thr0, s0 + cs.y + M0);
        if (s1 <= thr1) {
            if (cnt1 < CAP_) cl1[cnt1] = (unsigned short)k;
            ++cnt1;
        }
        thr1 = min(thr1, s1 + cs.y + M1);
    }

    // ---- phases 3+4 per token: exact rescore, output, loss ----
    float acc = 0.0f;
#pragma unroll 1
    for (int t = 0; t < 2; ++t) {
        const int tcol = (t == 0) ? t0 : t1;
        const int cnt  = (t == 0) ? cnt0 : cnt1;
        const unsigned short* cl = (t == 0) ? cl0 : cl1;
        const float* zc = zb + tcol;

        float zr[D_];
#pragma unroll
        for (int i = 0; i < D_; ++i) zr[i] = zc[(size_t)i << 12];
        float A = 0.0f;
#pragma unroll
        for (int i = 0; i < D_; ++i) A = fmaf(zr[i], zr[i], A);

        float bd = 3.402823466e38f;
        int bestk = 0;
        if (cnt <= CAP_) {
            for (int j = 0; j < cnt; ++j) {      // ascending k: first-min ties
                int k = cl[j];
                float dd = exact_dist_sm(zr, A, sm, k);
                if (dd < bd) { bd = dd; bestk = k; }
            }
        } else {                                  // overflow: full exact scan
            for (int k = 0; k < K_; ++k) {
                float dd = exact_dist_sm(zr, A, sm, k);
                if (dd < bd) { bd = dd; bestk = k; }
            }
        }

        const int n = (bidx << 12) + tcol;
        if (out_i) out_i[n] = (float)bestk;

        const float4* qr = reinterpret_cast<const float4*>(sm + SM_CBF + bestk * 272);
        float* oq = out_q ? out_q + ((size_t)bidx << 18) + tcol : nullptr;
#pragma unroll
        for (int j = 0; j < 16; ++j) {
            float4 qv = qr[j];
            float d0 = __fsub_rn(qv.x, zr[4 * j + 0]);
            float d1 = __fsub_rn(qv.y, zr[4 * j + 1]);
            float d2 = __fsub_rn(qv.z, zr[4 * j + 2]);
            float d3 = __fsub_rn(qv.w, zr[4 * j + 3]);
            if (oq) {
                oq[(size_t)(4 * j + 0) << 12] = __fadd_rn(zr[4 * j + 0], d0);
                oq[(size_t)(4 * j + 1) << 12] = __fadd_rn(zr[4 * j + 1], d1);
                oq[(size_t)(4 * j + 2) << 12] = __fadd_rn(zr[4 * j + 2], d2);
                oq[(size_t)(4 * j + 3) << 12] = __fadd_rn(zr[4 * j + 3], d3);
            }
            acc = fmaf(d0, d0, acc);
            acc = fmaf(d1, d1, acc);
            acc = fmaf(d2, d2, acc);
            acc = fmaf(d3, d3, acc);
        }
    }

#pragma unroll
    for (int o = 16; o > 0; o >>= 1) acc += __shfl_xor_sync(0xffffffffu, acc, o);
    if (lane == 0) s_wsum[wid] = acc;
    __syncthreads();
    if (tid == 0) {
        float s = 0.0f;
#pragma unroll
        for (int i = 0; i < 16; ++i) s += s_wsum[i];
        g_partial[blockIdx.x] = s;
        __threadfence();
        unsigned int ticket = atomicAdd(&g_count, 1u);
        s_last[0] = (ticket == 127u) ? 1 : 0;
    }
    __syncthreads();

    // ---- last block: deterministic finalize ----
    if (s_last[0]) {
        if (tid < 128) s_rd[tid] = (double)g_partial[tid];
        __syncthreads();
        for (int st = 64; st > 0; st >>= 1) {
            if (tid < st) s_rd[tid] += s_rd[tid + st];
            __syncthreads();
        }
        if (tid == 0) {
            if (loss_ptr) {
                float cl_ = (float)(s_rd[0] / (double)NQ_);
                loss_ptr[0] = __fadd_rn(cl_, __fmul_rn(0.25f, cl_));
            }
            g_count = 0;   // reset for next graph replay
        }
    }
}

// ---------------------------------------------------------------------------
extern "C" void kernel_launch(void* const* d_in, const int* in_sizes, int n_in,
                              void* d_out, int out_size) {
    const float* z  = nullptr;
    const float* cb = nullptr;
    for (int i = 0; i < n_in; ++i) {
        if (in_sizes[i] == NQ_)          z  = (const float*)d_in[i];
        else if (in_sizes[i] == K_ * D_) cb = (const float*)d_in[i];
    }
    if (!z || !cb) return;

    float* out = (float*)d_out;
    float* loss_ptr = nullptr;
    float* q_ptr    = nullptr;
    float* i_ptr    = nullptr;

    if (out_size == 1 + NQ_ + N_) {
        loss_ptr = out; q_ptr = out + 1; i_ptr = out + 1 + NQ_;
    } else if (out_size == NQ_ + N_) {
        q_ptr = out; i_ptr = out + NQ_;
    } else if (out_size == NQ_) {
        q_ptr = out;
    } else if (out_size == N_) {
        i_ptr = out;
    } else if (out_size == 1) {
        loss_ptr = out;
    } else if (out_size > 1 + NQ_ + N_) {
        loss_ptr = out; q_ptr = out + 1; i_ptr = out + 1 + NQ_;
    }

    static bool attr_done = false;
    if (!attr_done) {
        cudaFuncSetAttribute(vq_kernel,
                             cudaFuncAttributeMaxDynamicSharedMemorySize,
                             SM_TOT);
        attr_done = true;
    }

    prep_z_kernel<<<512, 256>>>(z);
    prep_cb1_kernel<<<2, 256>>>(cb);
    prep_cb2_kernel<<<2, 256>>>(cb);
    vq_kernel<<<N_ / 1024, 512, SM_TOT>>>(z, cb, q_ptr, i_ptr, loss_ptr);
}